// round 9
// baseline (speedup 1.0000x reference)
#include <cuda_runtime.h>
#include <cuda_bf16.h>

#define KDIM 8
static const int MAXN  = 100000;
static const int MAXE  = 3200000;
static const int MAXNK = MAXN * KDIM;

// ---- scratch (device globals; no cudaMalloc allowed) ----
__device__ float4 g_accQ4[MAXNK];   // seeded es*q, then += segment sums
__device__ float2 g_accDL2[MAXNK];  // seeded {es, es*l}
__device__ float4 g_qp[MAXNK];      // packed: max(l,1e-8)*q (norm encodes l)
__device__ int    g_count[MAXN];    // per-dst degree (memset to 0 each replay)
__device__ int    g_rank[MAXE];     // rank of edge within its dst bin
__device__ int    g_off[MAXN + 1];  // CSR offsets
__device__ int    g_blocklocal[MAXN];
__device__ int    g_blocksum[128];
__device__ int    g_blockbase[128];
__device__ float4 g_pay[2 * MAXE];  // sorted payload: [2p]=rel_q, [2p+1]={w,src,dst,-}

// ---------------------------------------------------------------------------
// Seed: packed node table + self-term seeding of accumulators.
// ---------------------------------------------------------------------------
__global__ void __launch_bounds__(256)
k_seed(const float* __restrict__ node_levels,
       const float4* __restrict__ node_q, int NK)
{
    int i = blockIdx.x * blockDim.x + threadIdx.x;
    if (i >= NK) return;
    float  l = node_levels[i];
    float4 q = node_q[i];
    float lc = fmaxf(l, 1e-8f);
    g_qp[i] = make_float4(lc * q.x, lc * q.y, lc * q.z, lc * q.w);
    float es = __expf(8.0f * l);          // self term (w=1); shift cancels
    g_accQ4[i]  = make_float4(es * q.x, es * q.y, es * q.z, es * q.w);
    g_accDL2[i] = make_float2(es, es * l);
}

// ---------------------------------------------------------------------------
// Histogram + rank.
// ---------------------------------------------------------------------------
__global__ void k_hist(const int* __restrict__ edge_dst, int E)
{
    int e = blockIdx.x * blockDim.x + threadIdx.x;
    if (e >= E) return;
    int d = __ldg(edge_dst + e);
    g_rank[e] = atomicAdd(&g_count[d], 1);
}

// ---------------------------------------------------------------------------
// Scan (3 stages) over g_count -> g_off.
// ---------------------------------------------------------------------------
__global__ void k_scanA(int N)
{
    int i = blockIdx.x * 1024 + threadIdx.x;
    int lane = threadIdx.x & 31, wid = threadIdx.x >> 5;
    int v = (i < N) ? g_count[i] : 0;
    int x = v;
    #pragma unroll
    for (int o = 1; o < 32; o <<= 1) {
        int y = __shfl_up_sync(0xffffffffu, x, o);
        if (lane >= o) x += y;
    }
    __shared__ int wsum[32];
    if (lane == 31) wsum[wid] = x;
    __syncthreads();
    if (wid == 0) {
        int s = wsum[lane];
        #pragma unroll
        for (int o = 1; o < 32; o <<= 1) {
            int y = __shfl_up_sync(0xffffffffu, s, o);
            if (lane >= o) s += y;
        }
        wsum[lane] = s;
    }
    __syncthreads();
    int incl = x + (wid > 0 ? wsum[wid - 1] : 0);
    if (i < N) g_blocklocal[i] = incl - v;
    if (threadIdx.x == 1023) g_blocksum[blockIdx.x] = incl;
}

__global__ void k_scanB(int nb)
{
    int t = threadIdx.x;                  // 128 threads
    int lane = t & 31, wid = t >> 5;
    int v = (t < nb) ? g_blocksum[t] : 0;
    int x = v;
    #pragma unroll
    for (int o = 1; o < 32; o <<= 1) {
        int y = __shfl_up_sync(0xffffffffu, x, o);
        if (lane >= o) x += y;
    }
    __shared__ int wsum[4];
    if (lane == 31) wsum[wid] = x;
    __syncthreads();
    int base = 0;
    for (int wp = 0; wp < wid; wp++) base += wsum[wp];
    if (t < nb) g_blockbase[t] = x + base - v;
}

__global__ void k_scanC(int N, int E)
{
    int i = blockIdx.x * blockDim.x + threadIdx.x;
    if (i > N) return;
    g_off[i] = (i < N) ? (g_blockbase[i >> 10] + g_blocklocal[i]) : E;
}

// ---------------------------------------------------------------------------
// Scatter payload into dst-sorted order (32B sector-exact stores).
// ---------------------------------------------------------------------------
__global__ void k_scatter(const float4* __restrict__ edge_rel_q,
                          const float*  __restrict__ edge_w,
                          const int*    __restrict__ edge_src,
                          const int*    __restrict__ edge_dst,
                          int E)
{
    int e = blockIdx.x * blockDim.x + threadIdx.x;
    if (e >= E) return;
    int d   = __ldg(edge_dst + e);
    int pos = g_off[d] + g_rank[e];
    float4 rq = __ldg(edge_rel_q + e);
    float  w  = __ldg(edge_w + e);
    int    s  = __ldg(edge_src + e);
    g_pay[2 * pos]     = rq;
    g_pay[2 * pos + 1] = make_float4(w, __int_as_float(s),
                                     __int_as_float(d), 0.f);
}

// ---------------------------------------------------------------------------
// Segmented gather-reduce over sorted slots. Warp covers 4 slots (j=lane>>3),
// k = lane&7. Same-dst runs are contiguous -> segmented suffix-sum over j via
// shuffles; only segment heads (avg ~1.125 per warp) emit REDs.
// ---------------------------------------------------------------------------
__global__ void __launch_bounds__(256)
k_reduce(int E)
{
    const unsigned FULL = 0xffffffffu;
    int wg   = (blockIdx.x * blockDim.x + threadIdx.x) >> 5;  // global warp id
    int lane = threadIdx.x & 31;
    int j = lane >> 3, k = lane & 7;

    long long s = (long long)wg * 4 + j;
    bool valid = (s < (long long)E);
    int  sc    = valid ? (int)s : (E - 1);     // clamp; masked by ee=0

    float4 rq   = __ldg(&g_pay[2 * sc]);
    float4 meta = __ldg(&g_pay[2 * sc + 1]);
    float w   = meta.x;
    int   src = __float_as_int(meta.y);
    int   dst = __float_as_int(meta.z);

    float4 qp = __ldg(&g_qp[src * KDIM + k]);  // 128B line per slot
    float nq   = qp.x*qp.x + qp.y*qp.y + qp.z*qp.z + qp.w*qp.w;
    float invl = rsqrtf(nq);
    float l    = nq * invl;

    float ee  = valid ? __expf(8.0f * w * l) : 0.f;
    float eel = ee * l;
    float scq = ee * invl;                     // qp = l*q -> scale by ee/l

    // Hamilton product rel_q (x) qp ; storage order (w,x,y,z)
    float vw = scq * (rq.x*qp.x - rq.y*qp.y - rq.z*qp.z - rq.w*qp.w);
    float vx = scq * (rq.x*qp.y + rq.y*qp.x + rq.z*qp.w - rq.w*qp.z);
    float vy = scq * (rq.x*qp.z - rq.y*qp.w + rq.z*qp.x + rq.w*qp.y);
    float vz = scq * (rq.x*qp.w + rq.y*qp.z - rq.z*qp.y + rq.w*qp.x);

    // keys at j+1, j+2 (sortedness: key[j+2]==key[j] implies key[j+1]==key[j])
    int dst_n1 = __shfl_down_sync(FULL, dst, 8);
    int dst_n2 = __shfl_down_sync(FULL, dst, 16);
    bool m1 = (j < 3) && (dst_n1 == dst);
    bool m2 = (j < 2) && (dst_n2 == dst);

    float t;
    // suffix step, distance 1 (8 lanes)
    t = __shfl_down_sync(FULL, vw, 8);  vw  += m1 ? t : 0.f;
    t = __shfl_down_sync(FULL, vx, 8);  vx  += m1 ? t : 0.f;
    t = __shfl_down_sync(FULL, vy, 8);  vy  += m1 ? t : 0.f;
    t = __shfl_down_sync(FULL, vz, 8);  vz  += m1 ? t : 0.f;
    t = __shfl_down_sync(FULL, ee, 8);  ee  += m1 ? t : 0.f;
    t = __shfl_down_sync(FULL, eel, 8); eel += m1 ? t : 0.f;
    // suffix step, distance 2 (16 lanes)
    t = __shfl_down_sync(FULL, vw, 16);  vw  += m2 ? t : 0.f;
    t = __shfl_down_sync(FULL, vx, 16);  vx  += m2 ? t : 0.f;
    t = __shfl_down_sync(FULL, vy, 16);  vy  += m2 ? t : 0.f;
    t = __shfl_down_sync(FULL, vz, 16);  vz  += m2 ? t : 0.f;
    t = __shfl_down_sync(FULL, ee, 16);  ee  += m2 ? t : 0.f;
    t = __shfl_down_sync(FULL, eel, 16); eel += m2 ? t : 0.f;

    // heads: first slot of a segment within the warp
    int dst_p1 = __shfl_up_sync(FULL, dst, 8);
    bool head = valid && ((j == 0) || (dst_p1 != dst));

    // pair DL across k (even k covers k and k+1) AFTER the segmented sum
    float ee_n  = __shfl_down_sync(FULL, ee, 1);
    float eel_n = __shfl_down_sync(FULL, eel, 1);

    if (head) {
        int di = dst * KDIM + k;
        float4* aq = g_accQ4 + di;
        asm volatile("red.global.add.v4.f32 [%0], {%1, %2, %3, %4};"
                     :: "l"(aq), "f"(vw), "f"(vx), "f"(vy), "f"(vz)
                     : "memory");
        if ((k & 1) == 0) {
            float4* adl = (float4*)(g_accDL2 + di);   // 16B aligned (di even)
            asm volatile("red.global.add.v4.f32 [%0], {%1, %2, %3, %4};"
                         :: "l"(adl), "f"(ee), "f"(eel), "f"(ee_n), "f"(eel_n)
                         : "memory");
        }
    }
}

// ---------------------------------------------------------------------------
// Finalize: divide + normalize (accumulators already include self term).
// ---------------------------------------------------------------------------
__global__ void __launch_bounds__(256)
k_final(float4* __restrict__ out_q, float* __restrict__ out_l, int NK)
{
    int i = blockIdx.x * blockDim.x + threadIdx.x;
    if (i >= NK) return;
    float2 dl  = g_accDL2[i];
    float4 a   = g_accQ4[i];
    float  inv = 1.0f / dl.x;
    float qw = a.x * inv, qx = a.y * inv, qy = a.z * inv, qz = a.w * inv;
    float nrm = sqrtf(qw*qw + qx*qx + qy*qy + qz*qz);
    float r   = 1.0f / fmaxf(nrm, 1e-12f);
    out_q[i] = make_float4(qw * r, qx * r, qy * r, qz * r);
    out_l[i] = dl.y * inv;
}

// ---------------------------------------------------------------------------
// Launch. Inputs: 0 node_levels [N,K], 1 node_q [N,K,4], 2 edge_rel_q [E,4],
//                 3 edge_w [E], 4 edge_src [E], 5 edge_dst [E].
// Output: q [N,K,4] flattened, then out_levels [N,K].
// ---------------------------------------------------------------------------
extern "C" void kernel_launch(void* const* d_in, const int* in_sizes, int n_in,
                              void* d_out, int out_size)
{
    const float*  node_levels = (const float*) d_in[0];
    const float4* node_q      = (const float4*)d_in[1];
    const float4* edge_rel_q  = (const float4*)d_in[2];
    const float*  edge_w      = (const float*) d_in[3];
    const int*    edge_src    = (const int*)   d_in[4];
    const int*    edge_dst    = (const int*)   d_in[5];

    int NK = in_sizes[0];
    int N  = NK / KDIM;
    int E  = in_sizes[3];

    float4* out_q = (float4*)d_out;
    float*  out_l = (float*)d_out + (long long)NK * 4;

    void* pCount = nullptr;
    cudaGetSymbolAddress(&pCount, g_count);
    cudaMemsetAsync(pCount, 0, (size_t)N * sizeof(int), 0);

    const int TPB = 256;
    int grid_nk = (NK + TPB - 1) / TPB;
    int grid_e  = (E + TPB - 1) / TPB;
    int nb      = (N + 1023) / 1024;

    long long red_threads = ((long long)(E + 3) / 4) * 32;
    int grid_red = (int)((red_threads + TPB - 1) / TPB);

    k_seed   <<<grid_nk, TPB>>>(node_levels, node_q, NK);
    k_hist   <<<grid_e, TPB>>>(edge_dst, E);
    k_scanA  <<<nb, 1024>>>(N);
    k_scanB  <<<1, 128>>>(nb);
    k_scanC  <<<(N + 1 + TPB - 1) / TPB, TPB>>>(N, E);
    k_scatter<<<grid_e, TPB>>>(edge_rel_q, edge_w, edge_src, edge_dst, E);
    k_reduce <<<grid_red, TPB>>>(E);
    k_final  <<<grid_nk, TPB>>>(out_q, out_l, NK);
}

// round 10
// speedup vs baseline: 1.6685x; 1.6685x over previous
#include <cuda_runtime.h>
#include <cuda_bf16.h>

#define KDIM 8
static const int MAXN  = 100000;
static const int MAXNK = MAXN * KDIM;

// Scratch (device globals — no cudaMalloc allowed).
__device__ float4 g_accQ4[MAXNK];   // seeded es*q, then += ee * (rel x q_src)
__device__ float2 g_accDL2[MAXNK];  // seeded {es, es*l}, then += {ee, ee*l}
__device__ float4 g_qp[MAXNK];      // packed: max(l,1e-8) * q  (norm encodes l)

// ---------------------------------------------------------------------------
// Prepass (2 elements/thread): build packed node table + seed accumulators
// with the self term. float2 level loads; paired DL seeds as one float4.
// ---------------------------------------------------------------------------
__global__ void __launch_bounds__(256)
spt_prep_kernel(const float2* __restrict__ node_levels2,
                const float4* __restrict__ node_q,
                int NK2)                         // NK/2
{
    int t = blockIdx.x * blockDim.x + threadIdx.x;
    if (t >= NK2) return;
    int i0 = 2 * t;

    float2 l2 = __ldg(node_levels2 + t);
    float4 q0 = __ldg(node_q + i0);
    float4 q1 = __ldg(node_q + i0 + 1);

    float lc0 = fmaxf(l2.x, 1e-8f);
    float lc1 = fmaxf(l2.y, 1e-8f);
    g_qp[i0]     = make_float4(lc0 * q0.x, lc0 * q0.y, lc0 * q0.z, lc0 * q0.w);
    g_qp[i0 + 1] = make_float4(lc1 * q1.x, lc1 * q1.y, lc1 * q1.z, lc1 * q1.w);

    float es0 = __expf(8.0f * l2.x);             // self term (w=1); shift cancels
    float es1 = __expf(8.0f * l2.y);
    g_accQ4[i0]     = make_float4(es0 * q0.x, es0 * q0.y, es0 * q0.z, es0 * q0.w);
    g_accQ4[i0 + 1] = make_float4(es1 * q1.x, es1 * q1.y, es1 * q1.z, es1 * q1.w);

    // two float2 DL seeds -> one aligned float4 store (i0 even)
    *(float4*)(g_accDL2 + i0) = make_float4(es0, es0 * l2.x, es1, es1 * l2.y);
}

// ---------------------------------------------------------------------------
// Edge scatter (byte-identical to R8): 2 (edge,k) elements per thread,
// t and t + halfEK; all loads issued up front; DL REDs before Hamilton FMAs.
// ---------------------------------------------------------------------------
__global__ void __launch_bounds__(256)
spt_edge_kernel(const float4* __restrict__ edge_rel_q,
                const float*  __restrict__ edge_w,
                const int*    __restrict__ edge_src,
                const int*    __restrict__ edge_dst,
                long long halfEK)
{
    long long t = (long long)blockIdx.x * blockDim.x + threadIdx.x;
    bool active = (t < halfEK);
    long long tc = active ? t : 0;        // clamp for safe loads
    long long u0 = tc;
    long long u1 = tc + halfEK;
    int e0 = (int)(u0 >> 3);
    int e1 = (int)(u1 >> 3);
    int k  = (int)(u0 & 7);               // same k for u1 (halfEK % 8 == 0)

    // ---- issue all loads up front ----
    int   s0 = __ldg(edge_src + e0);
    int   s1 = __ldg(edge_src + e1);
    int   d0 = __ldg(edge_dst + e0);
    int   d1 = __ldg(edge_dst + e1);
    float w0 = __ldg(edge_w + e0);
    float w1 = __ldg(edge_w + e1);
    float4 rq0 = __ldg(edge_rel_q + e0);
    float4 rq1 = __ldg(edge_rel_q + e1);
    float4 qp0 = __ldg(g_qp + s0 * KDIM + k);   // 128B line per edge
    float4 qp1 = __ldg(g_qp + s1 * KDIM + k);

    // ---- element 0 scalar chain ----
    float nq0   = qp0.x*qp0.x + qp0.y*qp0.y + qp0.z*qp0.z + qp0.w*qp0.w;
    float invl0 = rsqrtf(nq0);
    float l0    = nq0 * invl0;
    float ee0   = __expf(8.0f * w0 * l0);
    float eel0  = ee0 * l0;

    // ---- element 1 scalar chain ----
    float nq1   = qp1.x*qp1.x + qp1.y*qp1.y + qp1.z*qp1.z + qp1.w*qp1.w;
    float invl1 = rsqrtf(nq1);
    float l1    = nq1 * invl1;
    float ee1   = __expf(8.0f * w1 * l1);
    float eel1  = ee1 * l1;

    // ---- DL pairing via shfl (even lane k covers k and k+1) ----
    float nee0  = __shfl_down_sync(0xffffffffu, ee0,  1);
    float neel0 = __shfl_down_sync(0xffffffffu, eel0, 1);
    float nee1  = __shfl_down_sync(0xffffffffu, ee1,  1);
    float neel1 = __shfl_down_sync(0xffffffffu, eel1, 1);

    int di0 = d0 * KDIM + k;
    int di1 = d1 * KDIM + k;

    if (active && ((k & 1) == 0)) {
        float4* adl0 = (float4*)(g_accDL2 + di0);   // 16B aligned (di even)
        float4* adl1 = (float4*)(g_accDL2 + di1);
        asm volatile("red.global.add.v4.f32 [%0], {%1, %2, %3, %4};"
                     :: "l"(adl0), "f"(ee0), "f"(eel0), "f"(nee0), "f"(neel0)
                     : "memory");
        asm volatile("red.global.add.v4.f32 [%0], {%1, %2, %3, %4};"
                     :: "l"(adl1), "f"(ee1), "f"(eel1), "f"(nee1), "f"(neel1)
                     : "memory");
    }

    // ---- Hamilton products (rel_q x qp; qp = l*q so scale by ee/l) ----
    float sc0 = ee0 * invl0;
    float sc1 = ee1 * invl1;

    float aw0, ax0, ay0, az0;
    {
        float w1q = rq0.x, x1q = rq0.y, y1q = rq0.z, z1q = rq0.w;
        float w2q = qp0.x, x2q = qp0.y, y2q = qp0.z, z2q = qp0.w;
        aw0 = sc0 * (w1q*w2q - x1q*x2q - y1q*y2q - z1q*z2q);
        ax0 = sc0 * (w1q*x2q + x1q*w2q + y1q*z2q - z1q*y2q);
        ay0 = sc0 * (w1q*y2q - x1q*z2q + y1q*w2q + z1q*x2q);
        az0 = sc0 * (w1q*z2q + x1q*y2q - y1q*x2q + z1q*w2q);
    }
    float aw1, ax1, ay1, az1;
    {
        float w1q = rq1.x, x1q = rq1.y, y1q = rq1.z, z1q = rq1.w;
        float w2q = qp1.x, x2q = qp1.y, y2q = qp1.z, z2q = qp1.w;
        aw1 = sc1 * (w1q*w2q - x1q*x2q - y1q*y2q - z1q*z2q);
        ax1 = sc1 * (w1q*x2q + x1q*w2q + y1q*z2q - z1q*y2q);
        ay1 = sc1 * (w1q*y2q - x1q*z2q + y1q*w2q + z1q*x2q);
        az1 = sc1 * (w1q*z2q + x1q*y2q - y1q*x2q + z1q*w2q);
    }

    if (active) {
        float4* aq0 = g_accQ4 + di0;
        float4* aq1 = g_accQ4 + di1;
        asm volatile("red.global.add.v4.f32 [%0], {%1, %2, %3, %4};"
                     :: "l"(aq0), "f"(aw0), "f"(ax0), "f"(ay0), "f"(az0)
                     : "memory");
        asm volatile("red.global.add.v4.f32 [%0], {%1, %2, %3, %4};"
                     :: "l"(aq1), "f"(aw1), "f"(ax1), "f"(ay1), "f"(az1)
                     : "memory");
    }
}

// ---------------------------------------------------------------------------
// Finalize (2 elements/thread): divide + normalize; float4 DL reads,
// float2 out_l stores. Accumulators already include self term.
// ---------------------------------------------------------------------------
__global__ void __launch_bounds__(256)
spt_final_kernel(float4* __restrict__ out_q,
                 float2* __restrict__ out_l2,
                 int NK2)                        // NK/2
{
    int t = blockIdx.x * blockDim.x + threadIdx.x;
    if (t >= NK2) return;
    int i0 = 2 * t;

    float4 dl  = *(const float4*)(g_accDL2 + i0);   // {d0,l0,d1,l1}
    float4 a0  = g_accQ4[i0];
    float4 a1  = g_accQ4[i0 + 1];

    float inv0 = 1.0f / dl.x;
    float inv1 = 1.0f / dl.z;

    float qw0 = a0.x * inv0, qx0 = a0.y * inv0, qy0 = a0.z * inv0, qz0 = a0.w * inv0;
    float qw1 = a1.x * inv1, qx1 = a1.y * inv1, qy1 = a1.z * inv1, qz1 = a1.w * inv1;

    float n0 = sqrtf(qw0*qw0 + qx0*qx0 + qy0*qy0 + qz0*qz0);
    float n1 = sqrtf(qw1*qw1 + qx1*qx1 + qy1*qy1 + qz1*qz1);
    float r0 = 1.0f / fmaxf(n0, 1e-12f);
    float r1 = 1.0f / fmaxf(n1, 1e-12f);

    out_q[i0]     = make_float4(qw0 * r0, qx0 * r0, qy0 * r0, qz0 * r0);
    out_q[i0 + 1] = make_float4(qw1 * r1, qx1 * r1, qy1 * r1, qz1 * r1);
    out_l2[t] = make_float2(dl.y * inv0, dl.w * inv1);
}

// ---------------------------------------------------------------------------
// Launch. Inputs: 0 node_levels [N,K], 1 node_q [N,K,4], 2 edge_rel_q [E,4],
//                 3 edge_w [E], 4 edge_src [E], 5 edge_dst [E].
// Output: q [N,K,4] flattened, then out_levels [N,K].
// ---------------------------------------------------------------------------
extern "C" void kernel_launch(void* const* d_in, const int* in_sizes, int n_in,
                              void* d_out, int out_size)
{
    const float2* node_levels2 = (const float2*)d_in[0];
    const float4* node_q       = (const float4*)d_in[1];
    const float4* edge_rel_q   = (const float4*)d_in[2];
    const float*  edge_w       = (const float*) d_in[3];
    const int*    edge_src     = (const int*)   d_in[4];
    const int*    edge_dst     = (const int*)   d_in[5];

    int NK  = in_sizes[0];                // N*K (even)
    int NK2 = NK / 2;
    int E   = in_sizes[3];
    long long EK = (long long)E * KDIM;
    long long halfEK = EK / 2;            // E even -> halfEK % 8 == 0

    float4* out_q  = (float4*)d_out;
    float2* out_l2 = (float2*)((float*)d_out + (long long)NK * 4);

    const int TPB = 256;
    int grid_nk2 = (NK2 + TPB - 1) / TPB;
    int grid_e2  = (int)((halfEK + TPB - 1) / TPB);

    spt_prep_kernel <<<grid_nk2, TPB>>>(node_levels2, node_q, NK2);
    spt_edge_kernel <<<grid_e2, TPB>>>(edge_rel_q, edge_w, edge_src,
                                       edge_dst, halfEK);
    spt_final_kernel<<<grid_nk2, TPB>>>(out_q, out_l2, NK2);
}

// round 11
// speedup vs baseline: 1.8059x; 1.0824x over previous
#include <cuda_runtime.h>
#include <cuda_bf16.h>
#include <cuda_fp16.h>

#define KDIM 8
static const int MAXN  = 100000;
static const int MAXNK = MAXN * KDIM;

// Scratch (device globals — no cudaMalloc allowed).
__device__ float4 g_accQ4[MAXNK];   // seeded es*q, then += ee * (rel x q_src)
__device__ float2 g_accDL2[MAXNK];  // seeded {es, es*l}, then += {ee, ee*l}
__device__ uint2  g_qh[MAXNK];      // half4-packed node_q (8B per (node,k))

// ---------------------------------------------------------------------------
// Prepass (scalar, 1 elem/thread — R8 shape): build half4 node table + seed
// accumulators with the self term (w=1 -> score 8*l). Self term uses fp32 q.
// ---------------------------------------------------------------------------
__global__ void __launch_bounds__(256)
spt_prep_kernel(const float* __restrict__ node_levels,
                const float4* __restrict__ node_q,
                int NK)
{
    int i = blockIdx.x * blockDim.x + threadIdx.x;
    if (i >= NK) return;
    float  l = node_levels[i];
    float4 q = node_q[i];

    __half2 h01 = __floats2half2_rn(q.x, q.y);
    __half2 h23 = __floats2half2_rn(q.z, q.w);
    uint2 packed;
    packed.x = *(unsigned int*)&h01;
    packed.y = *(unsigned int*)&h23;
    g_qh[i] = packed;

    float es = __expf(8.0f * l);          // self term; softmax shift cancels
    g_accQ4[i]  = make_float4(es * q.x, es * q.y, es * q.z, es * q.w);
    g_accDL2[i] = make_float2(es, es * l);
}

// ---------------------------------------------------------------------------
// Edge scatter, 2 (edge,k) elements per thread: t and t + halfEK.
// Gathers: half4 q (64B/edge) + fp32 l from input node_levels (32B/edge).
// l stays exact -> softmax weights exact; only q carries fp16 quantization.
// All loads issued up front; DL REDs issued before Hamilton FMAs.
// ---------------------------------------------------------------------------
__global__ void __launch_bounds__(256)
spt_edge_kernel(const float*  __restrict__ node_levels,
                const float4* __restrict__ edge_rel_q,
                const float*  __restrict__ edge_w,
                const int*    __restrict__ edge_src,
                const int*    __restrict__ edge_dst,
                long long halfEK)
{
    long long t = (long long)blockIdx.x * blockDim.x + threadIdx.x;
    bool active = (t < halfEK);
    long long tc = active ? t : 0;        // clamp for safe loads
    long long u0 = tc;
    long long u1 = tc + halfEK;
    int e0 = (int)(u0 >> 3);
    int e1 = (int)(u1 >> 3);
    int k  = (int)(u0 & 7);               // same k for u1 (halfEK % 8 == 0)

    // ---- issue all loads up front ----
    int   s0 = __ldg(edge_src + e0);
    int   s1 = __ldg(edge_src + e1);
    int   d0 = __ldg(edge_dst + e0);
    int   d1 = __ldg(edge_dst + e1);
    float w0 = __ldg(edge_w + e0);
    float w1 = __ldg(edge_w + e1);
    float4 rq0 = __ldg(edge_rel_q + e0);
    float4 rq1 = __ldg(edge_rel_q + e1);
    int si0 = s0 * KDIM + k;
    int si1 = s1 * KDIM + k;
    uint2 qh0 = __ldg(g_qh + si0);        // 64B line per edge across 8 lanes
    uint2 qh1 = __ldg(g_qh + si1);
    float l0  = __ldg(node_levels + si0); // 32B sector per edge (exact l)
    float l1  = __ldg(node_levels + si1);

    // ---- unpack q (fp16 -> fp32) ----
    float2 a01 = __half22float2(*(__half2*)&qh0.x);
    float2 a23 = __half22float2(*(__half2*)&qh0.y);
    float2 b01 = __half22float2(*(__half2*)&qh1.x);
    float2 b23 = __half22float2(*(__half2*)&qh1.y);

    // ---- softmax weights (exact fp32 l) ----
    float ee0  = __expf(8.0f * w0 * l0);
    float eel0 = ee0 * l0;
    float ee1  = __expf(8.0f * w1 * l1);
    float eel1 = ee1 * l1;

    // ---- DL pairing via shfl (even lane k covers k and k+1) ----
    float nee0  = __shfl_down_sync(0xffffffffu, ee0,  1);
    float neel0 = __shfl_down_sync(0xffffffffu, eel0, 1);
    float nee1  = __shfl_down_sync(0xffffffffu, ee1,  1);
    float neel1 = __shfl_down_sync(0xffffffffu, eel1, 1);

    int di0 = d0 * KDIM + k;
    int di1 = d1 * KDIM + k;

    if (active && ((k & 1) == 0)) {
        float4* adl0 = (float4*)(g_accDL2 + di0);   // 16B aligned (di even)
        float4* adl1 = (float4*)(g_accDL2 + di1);
        asm volatile("red.global.add.v4.f32 [%0], {%1, %2, %3, %4};"
                     :: "l"(adl0), "f"(ee0), "f"(eel0), "f"(nee0), "f"(neel0)
                     : "memory");
        asm volatile("red.global.add.v4.f32 [%0], {%1, %2, %3, %4};"
                     :: "l"(adl1), "f"(ee1), "f"(eel1), "f"(nee1), "f"(neel1)
                     : "memory");
    }

    // ---- Hamilton products: ee * (rel_q x q_src), storage (w,x,y,z) ----
    float aw0, ax0, ay0, az0;
    {
        float w1q = rq0.x, x1q = rq0.y, y1q = rq0.z, z1q = rq0.w;
        float w2q = a01.x, x2q = a01.y, y2q = a23.x, z2q = a23.y;
        aw0 = ee0 * (w1q*w2q - x1q*x2q - y1q*y2q - z1q*z2q);
        ax0 = ee0 * (w1q*x2q + x1q*w2q + y1q*z2q - z1q*y2q);
        ay0 = ee0 * (w1q*y2q - x1q*z2q + y1q*w2q + z1q*x2q);
        az0 = ee0 * (w1q*z2q + x1q*y2q - y1q*x2q + z1q*w2q);
    }
    float aw1, ax1, ay1, az1;
    {
        float w1q = rq1.x, x1q = rq1.y, y1q = rq1.z, z1q = rq1.w;
        float w2q = b01.x, x2q = b01.y, y2q = b23.x, z2q = b23.y;
        aw1 = ee1 * (w1q*w2q - x1q*x2q - y1q*y2q - z1q*z2q);
        ax1 = ee1 * (w1q*x2q + x1q*w2q + y1q*z2q - z1q*y2q);
        ay1 = ee1 * (w1q*y2q - x1q*z2q + y1q*w2q + z1q*x2q);
        az1 = ee1 * (w1q*z2q + x1q*y2q - y1q*x2q + z1q*w2q);
    }

    if (active) {
        float4* aq0 = g_accQ4 + di0;
        float4* aq1 = g_accQ4 + di1;
        asm volatile("red.global.add.v4.f32 [%0], {%1, %2, %3, %4};"
                     :: "l"(aq0), "f"(aw0), "f"(ax0), "f"(ay0), "f"(az0)
                     : "memory");
        asm volatile("red.global.add.v4.f32 [%0], {%1, %2, %3, %4};"
                     :: "l"(aq1), "f"(aw1), "f"(ax1), "f"(ay1), "f"(az1)
                     : "memory");
    }
}

// ---------------------------------------------------------------------------
// Finalize (scalar, 1 elem/thread — R8 shape): divide + normalize.
// Accumulators already include the self term.
// ---------------------------------------------------------------------------
__global__ void __launch_bounds__(256)
spt_final_kernel(float4* __restrict__ out_q,
                 float*  __restrict__ out_l,
                 int NK)
{
    int i = blockIdx.x * blockDim.x + threadIdx.x;
    if (i >= NK) return;

    float2 dl  = g_accDL2[i];
    float4 a   = g_accQ4[i];
    float  inv = 1.0f / dl.x;

    float qw = a.x * inv, qx = a.y * inv, qy = a.z * inv, qz = a.w * inv;
    float nrm = sqrtf(qw*qw + qx*qx + qy*qy + qz*qz);
    float r   = 1.0f / fmaxf(nrm, 1e-12f);
    out_q[i] = make_float4(qw * r, qx * r, qy * r, qz * r);
    out_l[i] = dl.y * inv;
}

// ---------------------------------------------------------------------------
// Launch. Inputs: 0 node_levels [N,K], 1 node_q [N,K,4], 2 edge_rel_q [E,4],
//                 3 edge_w [E], 4 edge_src [E], 5 edge_dst [E].
// Output: q [N,K,4] flattened, then out_levels [N,K].
// ---------------------------------------------------------------------------
extern "C" void kernel_launch(void* const* d_in, const int* in_sizes, int n_in,
                              void* d_out, int out_size)
{
    const float*  node_levels = (const float*) d_in[0];
    const float4* node_q      = (const float4*)d_in[1];
    const float4* edge_rel_q  = (const float4*)d_in[2];
    const float*  edge_w      = (const float*) d_in[3];
    const int*    edge_src    = (const int*)   d_in[4];
    const int*    edge_dst    = (const int*)   d_in[5];

    int NK = in_sizes[0];                 // N*K
    int E  = in_sizes[3];
    long long EK = (long long)E * KDIM;
    long long halfEK = EK / 2;            // E even -> halfEK % 8 == 0

    float4* out_q = (float4*)d_out;
    float*  out_l = (float*)d_out + (long long)NK * 4;

    const int TPB = 256;
    int grid_nk = (NK + TPB - 1) / TPB;
    int grid_e2 = (int)((halfEK + TPB - 1) / TPB);

    spt_prep_kernel <<<grid_nk, TPB>>>(node_levels, node_q, NK);
    spt_edge_kernel <<<grid_e2, TPB>>>(node_levels, edge_rel_q, edge_w,
                                       edge_src, edge_dst, halfEK);
    spt_final_kernel<<<grid_nk, TPB>>>(out_q, out_l, NK);
}